// round 2
// baseline (speedup 1.0000x reference)
#include <cuda_runtime.h>
#include <cuda_bf16.h>

// StateSpaceLayer: out[b,t,r,c] = sum_{j<=t} A[r]^(t-j) * x[b,j,r,c]
// == linear recurrence y_t = A[r]*y_{t-1} + x_t per (b,r,c) lane.
// Shapes: x (B,SEQ,D,D) fp32, A (D,) fp32, out (B,SEQ,D,D) fp32.
// B=4, SEQ=512, D=64 for this problem instance (B derived from sizes).

#define SEQ   512
#define D     64
#define LCH   32          // timesteps per chunk (held in registers)
#define NC    (SEQ/LCH)   // 16 chunks
#define CH    32          // c-lanes per block (half of D)
#define TPB   (NC*CH)     // 512 threads

__global__ __launch_bounds__(TPB, 2)
void ssm_scan_kernel(const float* __restrict__ x,
                     const float* __restrict__ A,
                     float* __restrict__ out)
{
    // blockIdx.x encodes (b, r, c-half): grid = B * D * 2
    const int bid   = blockIdx.x;
    const int chalf = bid & 1;
    const int r     = (bid >> 1) & (D - 1);
    const int b     = bid >> 7;          // / (D*2)

    const int tid = threadIdx.x;
    const int cl  = tid & (CH - 1);      // c-lane within block
    const int k   = tid >> 5;            // chunk index 0..NC-1
    const int c   = cl + chalf * CH;

    const float a = fmaxf(A[r], 1e-6f);  // reference clips at EPS=1e-6

    // element (b, k*LCH + i, r, c); timestep stride = D*D floats
    const long base = ((long)(b * SEQ + k * LCH) * D + r) * D + c;
    const float* __restrict__ xp = x + base;

    // ---- load chunk into registers (32 independent coalesced LDGs) ----
    float v[LCH];
    #pragma unroll
    for (int i = 0; i < LCH; i++)
        v[i] = xp[(long)i * (D * D)];

    // ---- local inclusive scan within chunk ----
    #pragma unroll
    for (int i = 1; i < LCH; i++)
        v[i] = fmaf(a, v[i - 1], v[i]);

    // ---- cross-chunk carry combine ----
    __shared__ float s_end[NC][CH];
    __shared__ float s_pre[NC][CH];
    s_end[k][cl] = v[LCH - 1];
    __syncthreads();

    if (tid < CH) {
        // a^32 via 5 squarings
        float a2  = a * a;
        float a4  = a2 * a2;
        float a8  = a4 * a4;
        float a16 = a8 * a8;
        float a32 = a16 * a16;
        float carry = 0.0f;
        #pragma unroll
        for (int kk = 0; kk < NC; kk++) {
            s_pre[kk][tid] = carry;                       // exclusive prefix
            carry = fmaf(a32, carry, s_end[kk][tid]);     // E_k = s_k + a^L * E_{k-1}
        }
    }
    __syncthreads();

    // ---- apply carry and store: out_i = v_i + a^(i+1) * E ----
    const float E = s_pre[k][cl];
    float* __restrict__ op = out + base;
    float pw = a;
    #pragma unroll
    for (int i = 0; i < LCH; i++) {
        op[(long)i * (D * D)] = fmaf(pw, E, v[i]);
        pw *= a;
    }
}

extern "C" void kernel_launch(void* const* d_in, const int* in_sizes, int n_in,
                              void* d_out, int out_size)
{
    // Identify x vs A by element count (A has D=64 elements).
    const float* x = (const float*)d_in[0];
    const float* A = (const float*)d_in[1];
    long nx = in_sizes[0];
    if (n_in >= 2 && in_sizes[0] == D && in_sizes[1] > D) {
        x = (const float*)d_in[1];
        A = (const float*)d_in[0];
        nx = in_sizes[1];
    }
    const int B = (int)(nx / ((long)SEQ * D * D));   // 4

    float* out = (float*)d_out;
    dim3 grid(B * D * 2);
    dim3 block(TPB);
    ssm_scan_kernel<<<grid, block>>>(x, A, out);
}